// round 1
// baseline (speedup 1.0000x reference)
#include <cuda_runtime.h>
#include <cstdint>

#define N_NODES 131072
#define C_DIM   64
#define K_NEI   27
#define B_DIM   8
#define EMB_DIM 512
#define GN_EPS  1e-5f

typedef unsigned long long ull;

// ---------------- scratch (device globals; no allocation allowed) -----------
__device__ float g_h1[N_NODES * C_DIM];     // silu(gn(x)) / silu(gn(h2))
__device__ float g_h2[N_NODES * C_DIM];     // conv1 output + t
__device__ float g_sum[B_DIM * C_DIM];
__device__ float g_ssq[B_DIM * C_DIM];
__device__ float g_cnt[B_DIM];
__device__ float g_scale[B_DIM * C_DIM];
__device__ float g_shift[B_DIM * C_DIM];
__device__ float g_tvec[B_DIM * C_DIM];

// ---------------- f32x2 packed math helpers (sm_103a) -----------------------
__device__ __forceinline__ ull pack2(float x, float y) {
    ull r;
    asm("mov.b64 %0, {%1, %2};" : "=l"(r) : "f"(x), "f"(y));
    return r;
}
__device__ __forceinline__ void fma2(ull& d, ull a, ull b) {
    asm("fma.rn.f32x2 %0, %1, %2, %0;" : "+l"(d) : "l"(a), "l"(b));
}
__device__ __forceinline__ float2 unpack2(ull v) {
    float2 r;
    asm("mov.b64 {%0, %1}, %2;" : "=f"(r.x), "=f"(r.y) : "l"(v));
    return r;
}
__device__ __forceinline__ float silu_f(float v) {
    return v / (1.0f + __expf(-v));
}

// ---------------- zero stats -------------------------------------------------
__global__ void zero_kernel(float* gsum, float* gssq, float* gcnt, int do_cnt) {
    int i = threadIdx.x;            // 512 threads
    gsum[i] = 0.0f;
    gssq[i] = 0.0f;
    if (do_cnt && i < B_DIM) gcnt[i] = 0.0f;
}

// ---------------- per-(batch,channel) sum / sumsq ----------------------------
// 256 threads/block, 512 nodes/block. Thread = (channel c, row-phase r).
__global__ void stats_kernel(const float* __restrict__ in, const int* __restrict__ bid,
                             float* __restrict__ gsum, float* __restrict__ gssq,
                             float* __restrict__ gcnt, int do_cnt) {
    const int NPB = 512;
    int c = threadIdx.x & 63;
    int r = threadIdx.x >> 6;       // 0..3
    int base = blockIdx.x * NPB;

    float s = 0.0f, ss = 0.0f, cl = 0.0f;
    int cur = bid[base + r];
    for (int i = 0; i < NPB / 4; i++) {
        int n = base + i * 4 + r;
        int b = bid[n];
        if (b != cur) {
            atomicAdd(&gsum[cur * 64 + c], s);
            atomicAdd(&gssq[cur * 64 + c], ss);
            if (do_cnt && c == 0) atomicAdd(&gcnt[cur], cl);
            s = 0.0f; ss = 0.0f; cl = 0.0f; cur = b;
        }
        float v = in[(size_t)n * 64 + c];
        s += v; ss += v * v; cl += 1.0f;
    }
    atomicAdd(&gsum[cur * 64 + c], s);
    atomicAdd(&gssq[cur * 64 + c], ss);
    if (do_cnt && c == 0) atomicAdd(&gcnt[cur], cl);
}

// ---------------- finalize GN affine: per (b,c) scale/shift -------------------
// cpg = 2 : group g = c/2 covers channels (c&~1, c|1)
__global__ void finalize_kernel(const float* __restrict__ gsum, const float* __restrict__ gssq,
                                const float* __restrict__ gcnt,
                                const float* __restrict__ gamma, const float* __restrict__ beta,
                                float* __restrict__ scale, float* __restrict__ shift) {
    int i = threadIdx.x;            // 512 = B*C
    int b = i >> 6, c = i & 63;
    int g0 = c & ~1;
    float denom = gcnt[b] * 2.0f;
    float m = (gsum[b * 64 + g0] + gsum[b * 64 + g0 + 1]) / denom;
    float v = (gssq[b * 64 + g0] + gssq[b * 64 + g0 + 1]) / denom - m * m;
    float rs = rsqrtf(v + GN_EPS);
    float sc = gamma[c] * rs;
    scale[i] = sc;
    shift[i] = beta[c] - m * sc;
}

// ---------------- normalize + SiLU (vectorized) -------------------------------
__global__ void normact_kernel(const float4* __restrict__ in, const int* __restrict__ bid,
                               const float4* __restrict__ scale, const float4* __restrict__ shift,
                               float4* __restrict__ out) {
    int idx = blockIdx.x * blockDim.x + threadIdx.x;   // N*16
    int n = idx >> 4, q = idx & 15;
    int b = bid[n];
    float4 v = in[idx];
    float4 sc = scale[b * 16 + q];
    float4 sh = shift[b * 16 + q];
    float4 r;
    r.x = silu_f(v.x * sc.x + sh.x);
    r.y = silu_f(v.y * sc.y + sh.y);
    r.z = silu_f(v.z * sc.z + sh.z);
    r.w = silu_f(v.w * sc.w + sh.w);
    out[idx] = r;
}

// ---------------- time embedding: t[b,co] = silu(emb[b]) @ Wt + bt ------------
__global__ void time_kernel(const float* __restrict__ emb, const float* __restrict__ Wt,
                            const float* __restrict__ bt, float* __restrict__ tout) {
    __shared__ float se[B_DIM * EMB_DIM];      // 16KB
    int t = threadIdx.x;                       // 512
    for (int i = t; i < B_DIM * EMB_DIM; i += 512) {
        float v = emb[i];
        se[i] = silu_f(v);
    }
    __syncthreads();
    int b = t >> 6, co = t & 63;
    float acc = bt[co];
    const float* e = se + b * EMB_DIM;
    #pragma unroll 8
    for (int k = 0; k < EMB_DIM; k++)
        acc += e[k] * Wt[k * 64 + co];
    tout[t] = acc;
}

// ---------------- gather conv ---------------------------------------------------
// out[n,co] = sum_k sum_ci h[neigh[n,k], ci] * W[k, ci, co]  (+bias) (+t[bid]) (+resid)
// Block: 128 nodes, 256 threads. Thread tile: 4 nodes x 8 cout (FFMA2 over co-pairs).
#define TM 128
__global__ void __launch_bounds__(256) conv_kernel(
    const float* __restrict__ h, const int* __restrict__ neigh,
    const float* __restrict__ W, const float* __restrict__ bias,
    const float* __restrict__ tvec, const int* __restrict__ bid,
    const float* __restrict__ resid, float* __restrict__ out)
{
    __shared__ float sX[64 * TM];   // [ci][node]   32KB
    __shared__ float sW[64 * 64];   // [ci][co]     16KB

    const int t = threadIdx.x;
    const int base = blockIdx.x * TM;
    const int g  = t & 7;           // cout block: co = g*8 .. g*8+7
    const int jj = t >> 3;          // node quad: 4*jj .. 4*jj+3
    const int gn = t & 127;         // gather node
    const int gh = t >> 7;          // gather half-row (0/1)

    ull acc[4][4];
    #pragma unroll
    for (int a = 0; a < 4; a++)
        #pragma unroll
        for (int p = 0; p < 4; p++) acc[a][p] = 0ull;

    for (int k = 0; k < K_NEI; k++) {
        __syncthreads();   // previous compute done before smem overwrite
        // load W[k] slice (coalesced)
        {
            const float4* src = reinterpret_cast<const float4*>(W + k * 4096);
            float4* dst = reinterpret_cast<float4*>(sW);
            #pragma unroll
            for (int i = 0; i < 4; i++) dst[t + i * 256] = src[t + i * 256];
        }
        // gather 128 rows into transposed smem [ci][node]
        {
            int m = neigh[(base + gn) * K_NEI + k];
            const float4* src = reinterpret_cast<const float4*>(h + (size_t)m * 64 + gh * 32);
            #pragma unroll
            for (int i = 0; i < 8; i++) {
                float4 v = src[i];
                int c = gh * 32 + i * 4;
                sX[(c + 0) * TM + gn] = v.x;
                sX[(c + 1) * TM + gn] = v.y;
                sX[(c + 2) * TM + gn] = v.z;
                sX[(c + 3) * TM + gn] = v.w;
            }
        }
        __syncthreads();
        // compute: 4 nodes x 8 co, packed f32x2 over co pairs
        #pragma unroll 8
        for (int ci = 0; ci < 64; ci++) {
            float4 a = *reinterpret_cast<const float4*>(&sX[ci * TM + 4 * jj]);
            ull av0 = pack2(a.x, a.x);
            ull av1 = pack2(a.y, a.y);
            ull av2 = pack2(a.z, a.z);
            ull av3 = pack2(a.w, a.w);
            const ull* wr = reinterpret_cast<const ull*>(&sW[ci * 64 + g * 8]);
            #pragma unroll
            for (int p = 0; p < 4; p++) {
                ull w = wr[p];
                fma2(acc[0][p], av0, w);
                fma2(acc[1][p], av1, w);
                fma2(acc[2][p], av2, w);
                fma2(acc[3][p], av3, w);
            }
        }
    }

    // epilogue
    const int co0 = g * 8;
    float badd[8];
    #pragma unroll
    for (int j = 0; j < 8; j++) badd[j] = bias[co0 + j];

    #pragma unroll
    for (int a = 0; a < 4; a++) {
        int n = base + 4 * jj + a;
        float o[8];
        #pragma unroll
        for (int p = 0; p < 4; p++) {
            float2 v = unpack2(acc[a][p]);
            o[2 * p]     = v.x + badd[2 * p];
            o[2 * p + 1] = v.y + badd[2 * p + 1];
        }
        if (tvec) {
            int b = bid[n];
            #pragma unroll
            for (int j = 0; j < 8; j++) o[j] += tvec[b * 64 + co0 + j];
        }
        if (resid) {
            #pragma unroll
            for (int j = 0; j < 8; j++) o[j] += resid[(size_t)n * 64 + co0 + j];
        }
        float4* dst = reinterpret_cast<float4*>(out + (size_t)n * 64 + co0);
        dst[0] = make_float4(o[0], o[1], o[2], o[3]);
        dst[1] = make_float4(o[4], o[5], o[6], o[7]);
    }
}

// ---------------- launch --------------------------------------------------------
extern "C" void kernel_launch(void* const* d_in, const int* in_sizes, int n_in,
                              void* d_out, int out_size) {
    const float* x    = (const float*)d_in[0];
    const float* temb = (const float*)d_in[1];
    const int*   bid  = (const int*)  d_in[2];
    const int*   nei  = (const int*)  d_in[3];
    const float* ga1  = (const float*)d_in[4];
    const float* be1  = (const float*)d_in[5];
    const float* W1   = (const float*)d_in[6];
    const float* b1   = (const float*)d_in[7];
    const float* Wt   = (const float*)d_in[8];
    const float* bt   = (const float*)d_in[9];
    const float* ga2  = (const float*)d_in[10];
    const float* be2  = (const float*)d_in[11];
    const float* W2   = (const float*)d_in[12];
    const float* b2   = (const float*)d_in[13];
    float* out = (float*)d_out;

    float *h1, *h2, *sum, *ssq, *cnt, *scale, *shift, *tvec;
    cudaGetSymbolAddress((void**)&h1,    g_h1);
    cudaGetSymbolAddress((void**)&h2,    g_h2);
    cudaGetSymbolAddress((void**)&sum,   g_sum);
    cudaGetSymbolAddress((void**)&ssq,   g_ssq);
    cudaGetSymbolAddress((void**)&cnt,   g_cnt);
    cudaGetSymbolAddress((void**)&scale, g_scale);
    cudaGetSymbolAddress((void**)&shift, g_shift);
    cudaGetSymbolAddress((void**)&tvec,  g_tvec);

    const int statsBlocks = N_NODES / 512;       // 256
    const int naBlocks    = (N_NODES * 16) / 256; // 8192
    const int convBlocks  = N_NODES / TM;         // 1024

    // time embedding (independent)
    time_kernel<<<1, 512>>>(temb, Wt, bt, tvec);

    // GN1 -> silu -> h1
    zero_kernel<<<1, 512>>>(sum, ssq, cnt, 1);
    stats_kernel<<<statsBlocks, 256>>>(x, bid, sum, ssq, cnt, 1);
    finalize_kernel<<<1, 512>>>(sum, ssq, cnt, ga1, be1, scale, shift);
    normact_kernel<<<naBlocks, 256>>>((const float4*)x, bid,
                                      (const float4*)scale, (const float4*)shift,
                                      (float4*)h1);

    // conv1 + t[batch] -> h2
    conv_kernel<<<convBlocks, 256>>>(h1, nei, W1, b1, tvec, bid, nullptr, h2);

    // GN2 -> silu -> h1 (reuse)
    zero_kernel<<<1, 512>>>(sum, ssq, cnt, 0);
    stats_kernel<<<statsBlocks, 256>>>(h2, bid, sum, ssq, cnt, 0);
    finalize_kernel<<<1, 512>>>(sum, ssq, cnt, ga2, be2, scale, shift);
    normact_kernel<<<naBlocks, 256>>>((const float4*)h2, bid,
                                      (const float4*)scale, (const float4*)shift,
                                      (float4*)h1);

    // conv2 + residual -> out
    conv_kernel<<<convBlocks, 256>>>(h1, nei, W2, b2, nullptr, bid, x, out);
}

// round 3
// speedup vs baseline: 2.6741x; 2.6741x over previous
#include <cuda_runtime.h>
#include <cstdint>

#define N_NODES 131072
#define C_DIM   64
#define K_NEI   27
#define B_DIM   8
#define EMB_DIM 512
#define GN_EPS  1e-5f

// ---------------- scratch (device globals; no allocation allowed) -----------
__device__ float  g_h1[N_NODES * C_DIM];
__device__ float  g_h2[N_NODES * C_DIM];
__device__ float2 g_w1f[K_NEI * 2048];     // W1 in B-fragment order (tf32-rounded)
__device__ float2 g_w2f[K_NEI * 2048];     // W2 in B-fragment order
__device__ float  g_sum[B_DIM * C_DIM];
__device__ float  g_ssq[B_DIM * C_DIM];
__device__ float  g_cnt[B_DIM];
__device__ float  g_scale[B_DIM * C_DIM];
__device__ float  g_shift[B_DIM * C_DIM];
__device__ float  g_tvec[B_DIM * C_DIM];

// ---------------- helpers ----------------------------------------------------
__device__ __forceinline__ uint32_t smem_u32(const void* p) {
    uint32_t a;
    asm("{ .reg .u64 t; cvta.to.shared.u64 t, %1; cvt.u32.u64 %0, t; }" : "=r"(a) : "l"(p));
    return a;
}
__device__ __forceinline__ void cp16(uint32_t dst, const void* src) {
    asm volatile("cp.async.cg.shared.global [%0], [%1], 16;" :: "r"(dst), "l"(src) : "memory");
}
__device__ __forceinline__ void cp_commit() {
    asm volatile("cp.async.commit_group;" ::: "memory");
}
template <int N>
__device__ __forceinline__ void cp_wait() {
    asm volatile("cp.async.wait_group %0;" :: "n"(N) : "memory");
}
__device__ __forceinline__ float tf32r(float v) {
    uint32_t r;
    asm("cvt.rna.tf32.f32 %0, %1;" : "=r"(r) : "f"(v));
    return __uint_as_float(r);
}
__device__ __forceinline__ void mma_tf32(float* d, uint32_t a0, uint32_t a1, uint32_t a2,
                                         uint32_t a3, uint32_t b0, uint32_t b1) {
    asm volatile(
        "mma.sync.aligned.m16n8k8.row.col.f32.tf32.tf32.f32 "
        "{%0,%1,%2,%3}, {%4,%5,%6,%7}, {%8,%9}, {%0,%1,%2,%3};"
        : "+f"(d[0]), "+f"(d[1]), "+f"(d[2]), "+f"(d[3])
        : "r"(a0), "r"(a1), "r"(a2), "r"(a3), "r"(b0), "r"(b1));
}
__device__ __forceinline__ float silu_f(float v) { return v / (1.0f + __expf(-v)); }

// ---------------- GN helper kernels ------------------------------------------
__global__ void zero_kernel(float* gsum, float* gssq, float* gcnt, int do_cnt) {
    int i = threadIdx.x;
    gsum[i] = 0.0f; gssq[i] = 0.0f;
    if (do_cnt && i < B_DIM) gcnt[i] = 0.0f;
}

__global__ void stats_kernel(const float* __restrict__ in, const int* __restrict__ bid,
                             float* __restrict__ gsum, float* __restrict__ gssq,
                             float* __restrict__ gcnt, int do_cnt) {
    const int NPB = 512;
    int c = threadIdx.x & 63, r = threadIdx.x >> 6;
    int base = blockIdx.x * NPB;
    float s = 0.0f, ss = 0.0f, cl = 0.0f;
    int cur = bid[base + r];
    for (int i = 0; i < NPB / 4; i++) {
        int n = base + i * 4 + r;
        int b = bid[n];
        if (b != cur) {
            atomicAdd(&gsum[cur * 64 + c], s);
            atomicAdd(&gssq[cur * 64 + c], ss);
            if (do_cnt && c == 0) atomicAdd(&gcnt[cur], cl);
            s = 0.0f; ss = 0.0f; cl = 0.0f; cur = b;
        }
        float v = in[(size_t)n * 64 + c];
        s += v; ss += v * v; cl += 1.0f;
    }
    atomicAdd(&gsum[cur * 64 + c], s);
    atomicAdd(&gssq[cur * 64 + c], ss);
    if (do_cnt && c == 0) atomicAdd(&gcnt[cur], cl);
}

__global__ void finalize_kernel(const float* __restrict__ gsum, const float* __restrict__ gssq,
                                const float* __restrict__ gcnt,
                                const float* __restrict__ gamma, const float* __restrict__ beta,
                                float* __restrict__ scale, float* __restrict__ shift) {
    int i = threadIdx.x;
    int b = i >> 6, c = i & 63;
    int g0 = c & ~1;
    float denom = gcnt[b] * 2.0f;
    float m = (gsum[b * 64 + g0] + gsum[b * 64 + g0 + 1]) / denom;
    float v = (gssq[b * 64 + g0] + gssq[b * 64 + g0 + 1]) / denom - m * m;
    float rs = rsqrtf(v + GN_EPS);
    float sc = gamma[c] * rs;
    scale[i] = sc;
    shift[i] = beta[c] - m * sc;
}

// normalize + SiLU, output pre-rounded to tf32 (RN) for the MMA consumer
__global__ void normact_kernel(const float4* __restrict__ in, const int* __restrict__ bid,
                               const float4* __restrict__ scale, const float4* __restrict__ shift,
                               float4* __restrict__ out) {
    int idx = blockIdx.x * blockDim.x + threadIdx.x;
    int n = idx >> 4, q = idx & 15;
    int b = bid[n];
    float4 v = in[idx];
    float4 sc = scale[b * 16 + q];
    float4 sh = shift[b * 16 + q];
    float4 r;
    r.x = tf32r(silu_f(v.x * sc.x + sh.x));
    r.y = tf32r(silu_f(v.y * sc.y + sh.y));
    r.z = tf32r(silu_f(v.z * sc.z + sh.z));
    r.w = tf32r(silu_f(v.w * sc.w + sh.w));
    out[idx] = r;
}

__global__ void time_kernel(const float* __restrict__ emb, const float* __restrict__ Wt,
                            const float* __restrict__ bt, float* __restrict__ tout) {
    __shared__ float se[B_DIM * EMB_DIM];
    int t = threadIdx.x;
    for (int i = t; i < B_DIM * EMB_DIM; i += 512) se[i] = silu_f(emb[i]);
    __syncthreads();
    int b = t >> 6, co = t & 63;
    float acc = bt[co];
    const float* e = se + b * EMB_DIM;
    #pragma unroll 8
    for (int k = 0; k < EMB_DIM; k++) acc += e[k] * Wt[k * 64 + co];
    tout[t] = acc;
}

// ---------------- weight prep: W[k][ci][co] -> B-fragment order (tf32) -------
// per k: 8 ksteps (ci0=8s) x 8 cotiles (co0=8c) x 32 lanes, float2 {b0,b1}
//   b0 = W[k][ci0 + l%4    ][co0 + l/4]
//   b1 = W[k][ci0 + l%4 + 4][co0 + l/4]
__global__ void prep_w_kernel(const float* __restrict__ W, float2* __restrict__ Wf) {
    int i = blockIdx.x * 256 + threadIdx.x;      // over K_NEI*2048
    if (i >= K_NEI * 2048) return;
    int k = i >> 11;
    int r = i & 2047;
    int grp = r >> 5, lane = r & 31;
    int s = grp >> 3, c = grp & 7;
    int ci = s * 8 + (lane & 3);
    int co = c * 8 + (lane >> 2);
    const float* wk = W + (size_t)k * 4096;
    float2 v;
    v.x = tf32r(wk[ci * 64 + co]);
    v.y = tf32r(wk[(ci + 4) * 64 + co]);
    Wf[i] = v;
}

// ---------------- tf32 mma.sync gather-conv ----------------------------------
// 256 nodes/block, 512 threads (16 warps x 16 rows), Cout=64 in regs.
// Double-buffered cp.async staging of gathered rows + fragment weights.
#define TN        256
#define XS_STRIDE 68                          // floats per row (272B, 16B aligned)
#define XS_FLOATS (TN * XS_STRIDE)            // 17408 floats / buffer
#define WS_OFF    0                           // float2 ws[2][2048] : 32KB
#define XS_OFF    32768                       // float  xs[2][17408]: 139264B
#define SM_TOTAL  (32768 + 2 * XS_FLOATS * 4) // 172032

__global__ void __launch_bounds__(512, 1) conv_mma_kernel(
    const float* __restrict__ h, const int* __restrict__ neigh,
    const float2* __restrict__ wf, const float* __restrict__ bias,
    const float* __restrict__ tvec, const int* __restrict__ bid,
    const float* __restrict__ resid, float* __restrict__ out)
{
    extern __shared__ char smem[];
    float2* ws = reinterpret_cast<float2*>(smem + WS_OFF);
    float*  xs = reinterpret_cast<float*>(smem + XS_OFF);
    const uint32_t ws_sm = smem_u32(smem + WS_OFF);
    const uint32_t xs_sm = smem_u32(smem + XS_OFF);

    const int t = threadIdx.x;
    const int w = t >> 5, l = t & 31;
    const int base = blockIdx.x * TN;

    // gather role: 2 threads per row
    const int grow  = t >> 1;        // 0..255
    const int ghalf = t & 1;         // 0/1 -> 128B half of the 256B row

    float acc[8][4];
    #pragma unroll
    for (int c = 0; c < 8; c++)
        #pragma unroll
        for (int j = 0; j < 4; j++) acc[c][j] = 0.0f;

    // ---- stage k into buffer (k&1) -----------------------------------------
    auto issue = [&](int k) {
        const int buf = k & 1;
        // weights: 16KB linear, 2x16B per thread
        {
            const char* src = reinterpret_cast<const char*>(wf + (size_t)k * 2048);
            uint32_t dst = ws_sm + buf * 16384 + t * 32;
            cp16(dst,      src + t * 32);
            cp16(dst + 16, src + t * 32 + 16);
        }
        // gather: this thread's 128B half-row
        {
            int nb = neigh[(base + grow) * K_NEI + k];
            const char* src = reinterpret_cast<const char*>(h + (size_t)nb * 64) + ghalf * 128;
            uint32_t dst = xs_sm + buf * (XS_FLOATS * 4) + grow * (XS_STRIDE * 4) + ghalf * 128;
            #pragma unroll
            for (int j = 0; j < 8; j++) cp16(dst + j * 16, src + j * 16);
        }
        cp_commit();
    };

    issue(0);
    issue(1);

    const int g = l >> 2, tig = l & 3;

    for (int k = 0; k < K_NEI; k++) {
        cp_wait<1>();          // group k complete
        __syncthreads();

        const int buf = k & 1;
        const float*  xb = xs + buf * XS_FLOATS + (w * 16) * XS_STRIDE;
        const float2* wb = ws + buf * 2048;

        #pragma unroll
        for (int s = 0; s < 8; s++) {
            const float* ap = xb + g * XS_STRIDE + s * 8 + tig;
            uint32_t a0 = __float_as_uint(ap[0]);
            uint32_t a2 = __float_as_uint(ap[4]);
            uint32_t a1 = __float_as_uint(ap[8 * XS_STRIDE]);
            uint32_t a3 = __float_as_uint(ap[8 * XS_STRIDE + 4]);
            #pragma unroll
            for (int c = 0; c < 8; c++) {
                float2 b = wb[(s * 8 + c) * 32 + l];
                mma_tf32(acc[c], a0, a1, a2, a3,
                         __float_as_uint(b.x), __float_as_uint(b.y));
            }
        }
        __syncthreads();       // all warps done with buf before refill
        if (k + 2 < K_NEI) issue(k + 2);
    }

    // ---- epilogue: bias (+tvec) (+resid), direct STG ------------------------
    const int r0 = base + w * 16 + g;
    const int r1 = r0 + 8;
    float2 tv0 = make_float2(0.f, 0.f), tv1 = make_float2(0.f, 0.f);
    const float* tvp0 = nullptr; const float* tvp1 = nullptr;
    if (tvec) {
        tvp0 = tvec + (size_t)bid[r0] * 64;
        tvp1 = tvec + (size_t)bid[r1] * 64;
    }
    #pragma unroll
    for (int c = 0; c < 8; c++) {
        int co = c * 8 + 2 * tig;
        float2 bb = *reinterpret_cast<const float2*>(bias + co);
        float2 o0 = make_float2(acc[c][0] + bb.x, acc[c][1] + bb.y);
        float2 o1 = make_float2(acc[c][2] + bb.x, acc[c][3] + bb.y);
        if (tvec) {
            tv0 = *reinterpret_cast<const float2*>(tvp0 + co);
            tv1 = *reinterpret_cast<const float2*>(tvp1 + co);
            o0.x += tv0.x; o0.y += tv0.y;
            o1.x += tv1.x; o1.y += tv1.y;
        }
        if (resid) {
            float2 q0 = *reinterpret_cast<const float2*>(resid + (size_t)r0 * 64 + co);
            float2 q1 = *reinterpret_cast<const float2*>(resid + (size_t)r1 * 64 + co);
            o0.x += q0.x; o0.y += q0.y;
            o1.x += q1.x; o1.y += q1.y;
        }
        *reinterpret_cast<float2*>(out + (size_t)r0 * 64 + co) = o0;
        *reinterpret_cast<float2*>(out + (size_t)r1 * 64 + co) = o1;
    }
}

// ---------------- launch ------------------------------------------------------
extern "C" void kernel_launch(void* const* d_in, const int* in_sizes, int n_in,
                              void* d_out, int out_size) {
    const float* x    = (const float*)d_in[0];
    const float* temb = (const float*)d_in[1];
    const int*   bid  = (const int*)  d_in[2];
    const int*   nei  = (const int*)  d_in[3];
    const float* ga1  = (const float*)d_in[4];
    const float* be1  = (const float*)d_in[5];
    const float* W1   = (const float*)d_in[6];
    const float* b1   = (const float*)d_in[7];
    const float* Wt   = (const float*)d_in[8];
    const float* bt   = (const float*)d_in[9];
    const float* ga2  = (const float*)d_in[10];
    const float* be2  = (const float*)d_in[11];
    const float* W2   = (const float*)d_in[12];
    const float* b2   = (const float*)d_in[13];
    float* out = (float*)d_out;

    float *h1, *h2, *sum, *ssq, *cnt, *scale, *shift, *tvec;
    float2 *w1f, *w2f;
    cudaGetSymbolAddress((void**)&h1,    g_h1);
    cudaGetSymbolAddress((void**)&h2,    g_h2);
    cudaGetSymbolAddress((void**)&w1f,   g_w1f);
    cudaGetSymbolAddress((void**)&w2f,   g_w2f);
    cudaGetSymbolAddress((void**)&sum,   g_sum);
    cudaGetSymbolAddress((void**)&ssq,   g_ssq);
    cudaGetSymbolAddress((void**)&cnt,   g_cnt);
    cudaGetSymbolAddress((void**)&scale, g_scale);
    cudaGetSymbolAddress((void**)&shift, g_shift);
    cudaGetSymbolAddress((void**)&tvec,  g_tvec);

    cudaFuncSetAttribute(conv_mma_kernel,
                         cudaFuncAttributeMaxDynamicSharedMemorySize, SM_TOTAL);

    const int statsBlocks = N_NODES / 512;
    const int naBlocks    = (N_NODES * 16) / 256;
    const int convBlocks  = N_NODES / TN;                    // 512
    const int prepBlocks  = (K_NEI * 2048 + 255) / 256;      // 216

    // independent prep
    prep_w_kernel<<<prepBlocks, 256>>>(W1, w1f);
    prep_w_kernel<<<prepBlocks, 256>>>(W2, w2f);
    time_kernel<<<1, 512>>>(temb, Wt, bt, tvec);

    // GN1 -> silu -> h1 (tf32-rounded)
    zero_kernel<<<1, 512>>>(sum, ssq, cnt, 1);
    stats_kernel<<<statsBlocks, 256>>>(x, bid, sum, ssq, cnt, 1);
    finalize_kernel<<<1, 512>>>(sum, ssq, cnt, ga1, be1, scale, shift);
    normact_kernel<<<naBlocks, 256>>>((const float4*)x, bid,
                                      (const float4*)scale, (const float4*)shift,
                                      (float4*)h1);

    // conv1 (tf32 mma.sync) + t[batch] -> h2
    conv_mma_kernel<<<convBlocks, 512, SM_TOTAL>>>(h1, nei, w1f, b1, tvec, bid, nullptr, h2);

    // GN2 -> silu -> h1 (tf32-rounded)
    zero_kernel<<<1, 512>>>(sum, ssq, cnt, 0);
    stats_kernel<<<statsBlocks, 256>>>(h2, bid, sum, ssq, cnt, 0);
    finalize_kernel<<<1, 512>>>(sum, ssq, cnt, ga2, be2, scale, shift);
    normact_kernel<<<naBlocks, 256>>>((const float4*)h2, bid,
                                      (const float4*)scale, (const float4*)shift,
                                      (float4*)h1);

    // conv2 (tf32 mma.sync) + residual -> out
    conv_mma_kernel<<<convBlocks, 512, SM_TOTAL>>>(h1, nei, w2f, b2, nullptr, bid, x, out);
}

// round 4
// speedup vs baseline: 2.7365x; 1.0234x over previous
#include <cuda_runtime.h>
#include <cstdint>

#define N_NODES 131072
#define C_DIM   64
#define K_NEI   27
#define B_DIM   8
#define EMB_DIM 512
#define GN_EPS  1e-5f

// ---------------- scratch (device globals; no allocation allowed) -----------
__device__ float  g_h1[N_NODES * C_DIM];
__device__ float  g_h2[N_NODES * C_DIM];
__device__ float2 g_w1f[K_NEI * 2048];     // W1 in B-fragment order (tf32-rounded)
__device__ float2 g_w2f[K_NEI * 2048];     // W2 in B-fragment order
__device__ float  g_sum[B_DIM * C_DIM];
__device__ float  g_ssq[B_DIM * C_DIM];
__device__ float  g_cnt[B_DIM];
__device__ float  g_scale[B_DIM * C_DIM];
__device__ float  g_shift[B_DIM * C_DIM];
__device__ float  g_tvec[B_DIM * C_DIM];

// ---------------- helpers ----------------------------------------------------
__device__ __forceinline__ uint32_t smem_u32(const void* p) {
    uint32_t a;
    asm("{ .reg .u64 t; cvta.to.shared.u64 t, %1; cvt.u32.u64 %0, t; }" : "=r"(a) : "l"(p));
    return a;
}
__device__ __forceinline__ void cp16(uint32_t dst, const void* src) {
    asm volatile("cp.async.cg.shared.global [%0], [%1], 16;" :: "r"(dst), "l"(src) : "memory");
}
__device__ __forceinline__ void cp_commit() {
    asm volatile("cp.async.commit_group;" ::: "memory");
}
template <int N>
__device__ __forceinline__ void cp_wait() {
    asm volatile("cp.async.wait_group %0;" :: "n"(N) : "memory");
}
__device__ __forceinline__ float tf32r(float v) {
    uint32_t r;
    asm("cvt.rna.tf32.f32 %0, %1;" : "=r"(r) : "f"(v));
    return __uint_as_float(r);
}
__device__ __forceinline__ void mma_tf32(float* d, uint32_t a0, uint32_t a1, uint32_t a2,
                                         uint32_t a3, uint32_t b0, uint32_t b1) {
    asm volatile(
        "mma.sync.aligned.m16n8k8.row.col.f32.tf32.tf32.f32 "
        "{%0,%1,%2,%3}, {%4,%5,%6,%7}, {%8,%9}, {%0,%1,%2,%3};"
        : "+f"(d[0]), "+f"(d[1]), "+f"(d[2]), "+f"(d[3])
        : "r"(a0), "r"(a1), "r"(a2), "r"(a3), "r"(b0), "r"(b1));
}
__device__ __forceinline__ float silu_f(float v) { return v / (1.0f + __expf(-v)); }

// ---------------- GN helper kernels ------------------------------------------
__global__ void zero_kernel(float* gsum, float* gssq, float* gcnt) {
    int i = threadIdx.x;
    gsum[i] = 0.0f; gssq[i] = 0.0f;
    if (i < B_DIM) gcnt[i] = 0.0f;
}

__global__ void stats_kernel(const float* __restrict__ in, const int* __restrict__ bid,
                             float* __restrict__ gsum, float* __restrict__ gssq,
                             float* __restrict__ gcnt, int do_cnt) {
    const int NPB = 512;
    int c = threadIdx.x & 63, r = threadIdx.x >> 6;
    int base = blockIdx.x * NPB;
    float s = 0.0f, ss = 0.0f, cl = 0.0f;
    int cur = bid[base + r];
    for (int i = 0; i < NPB / 4; i++) {
        int n = base + i * 4 + r;
        int b = bid[n];
        if (b != cur) {
            atomicAdd(&gsum[cur * 64 + c], s);
            atomicAdd(&gssq[cur * 64 + c], ss);
            if (do_cnt && c == 0) atomicAdd(&gcnt[cur], cl);
            s = 0.0f; ss = 0.0f; cl = 0.0f; cur = b;
        }
        float v = in[(size_t)n * 64 + c];
        s += v; ss += v * v; cl += 1.0f;
    }
    atomicAdd(&gsum[cur * 64 + c], s);
    atomicAdd(&gssq[cur * 64 + c], ss);
    if (do_cnt && c == 0) atomicAdd(&gcnt[cur], cl);
}

// computes scale/shift, then (optionally) re-zeroes sum/ssq for the next GN pass
__global__ void finalize_kernel(float* __restrict__ gsum, float* __restrict__ gssq,
                                const float* __restrict__ gcnt,
                                const float* __restrict__ gamma, const float* __restrict__ beta,
                                float* __restrict__ scale, float* __restrict__ shift,
                                int zero_after) {
    int i = threadIdx.x;
    int b = i >> 6, c = i & 63;
    int g0 = c & ~1;
    float denom = gcnt[b] * 2.0f;
    float m = (gsum[b * 64 + g0] + gsum[b * 64 + g0 + 1]) / denom;
    float v = (gssq[b * 64 + g0] + gssq[b * 64 + g0 + 1]) / denom - m * m;
    float rs = rsqrtf(v + GN_EPS);
    float sc = gamma[c] * rs;
    scale[i] = sc;
    shift[i] = beta[c] - m * sc;
    if (zero_after) {
        __syncthreads();
        gsum[i] = 0.0f;
        gssq[i] = 0.0f;
    }
}

// normalize + SiLU, output pre-rounded to tf32 (RN) for the MMA consumer
__global__ void normact_kernel(const float4* __restrict__ in, const int* __restrict__ bid,
                               const float4* __restrict__ scale, const float4* __restrict__ shift,
                               float4* __restrict__ out) {
    int idx = blockIdx.x * blockDim.x + threadIdx.x;
    int n = idx >> 4, q = idx & 15;
    int b = bid[n];
    float4 v = in[idx];
    float4 sc = scale[b * 16 + q];
    float4 sh = shift[b * 16 + q];
    float4 r;
    r.x = tf32r(silu_f(v.x * sc.x + sh.x));
    r.y = tf32r(silu_f(v.y * sc.y + sh.y));
    r.z = tf32r(silu_f(v.z * sc.z + sh.z));
    r.w = tf32r(silu_f(v.w * sc.w + sh.w));
    out[idx] = r;
}

__global__ void time_kernel(const float* __restrict__ emb, const float* __restrict__ Wt,
                            const float* __restrict__ bt, float* __restrict__ tout) {
    __shared__ float se[B_DIM * EMB_DIM];
    int t = threadIdx.x;
    for (int i = t; i < B_DIM * EMB_DIM; i += 512) se[i] = silu_f(emb[i]);
    __syncthreads();
    int b = t >> 6, co = t & 63;
    float acc = bt[co];
    const float* e = se + b * EMB_DIM;
    #pragma unroll 8
    for (int k = 0; k < EMB_DIM; k++) acc += e[k] * Wt[k * 64 + co];
    tout[t] = acc;
}

// ---------------- weight prep: W[k][ci][co] -> B-fragment order (tf32) -------
__global__ void prep_w_kernel(const float* __restrict__ W, float2* __restrict__ Wf) {
    int i = blockIdx.x * 256 + threadIdx.x;      // over K_NEI*2048
    if (i >= K_NEI * 2048) return;
    int k = i >> 11;
    int r = i & 2047;
    int grp = r >> 5, lane = r & 31;
    int s = grp >> 3, c = grp & 7;
    int ci = s * 8 + (lane & 3);
    int co = c * 8 + (lane >> 2);
    const float* wk = W + (size_t)k * 4096;
    float2 v;
    v.x = tf32r(wk[ci * 64 + co]);
    v.y = tf32r(wk[(ci + 4) * 64 + co]);
    Wf[i] = v;
}

// ---------------- tf32 mma.sync gather-conv ----------------------------------
// 256 nodes/block, 256 threads (8 warps), each warp computes 32 rows x 64 co
// (two m16 tiles share every weight fragment -> 2x weight-LDS amortization).
#define TN        256
#define XS_STRIDE 68                          // floats per row (272B, 16B aligned)
#define XS_FLOATS (TN * XS_STRIDE)            // 17408 floats / buffer
#define WS_OFF    0                           // float2 ws[2][2048] : 32KB
#define XS_OFF    32768                       // float  xs[2][17408]: 139264B
#define SM_TOTAL  (32768 + 2 * XS_FLOATS * 4) // 172032

__global__ void __launch_bounds__(256, 1) conv_mma_kernel(
    const float* __restrict__ h, const int* __restrict__ neigh,
    const float2* __restrict__ wf, const float* __restrict__ bias,
    const float* __restrict__ tvec, const int* __restrict__ bid,
    const float* __restrict__ resid, float* __restrict__ out)
{
    extern __shared__ char smem[];
    float2* ws = reinterpret_cast<float2*>(smem + WS_OFF);
    float*  xs = reinterpret_cast<float*>(smem + XS_OFF);
    const uint32_t ws_sm = smem_u32(smem + WS_OFF);
    const uint32_t xs_sm = smem_u32(smem + XS_OFF);

    const int t = threadIdx.x;
    const int w = t >> 5, l = t & 31;
    const int base = blockIdx.x * TN;

    // preload this thread's 27 neighbor ids (1 row per thread)
    int nb[K_NEI];
    #pragma unroll
    for (int k = 0; k < K_NEI; k++) nb[k] = neigh[(base + t) * K_NEI + k];

    float acc[2][8][4];
    #pragma unroll
    for (int ti = 0; ti < 2; ti++)
        #pragma unroll
        for (int c = 0; c < 8; c++)
            #pragma unroll
            for (int j = 0; j < 4; j++) acc[ti][c][j] = 0.0f;

    // ---- stage k into buffer (k&1) -----------------------------------------
    auto issue = [&](int k) {
        const int buf = k & 1;
        // weights: 16KB linear, 4x16B per thread
        {
            const char* src = reinterpret_cast<const char*>(wf + (size_t)k * 2048) + t * 64;
            uint32_t dst = ws_sm + buf * 16384 + t * 64;
            #pragma unroll
            for (int j = 0; j < 4; j++) cp16(dst + j * 16, src + j * 16);
        }
        // gather: this thread's full 256B row
        {
            const char* src = reinterpret_cast<const char*>(h + (size_t)nb[k] * 64);
            uint32_t dst = xs_sm + buf * (XS_FLOATS * 4) + t * (XS_STRIDE * 4);
            #pragma unroll
            for (int j = 0; j < 16; j++) cp16(dst + j * 16, src + j * 16);
        }
        cp_commit();
    };

    issue(0);
    issue(1);

    const int g = l >> 2, tig = l & 3;

    for (int k = 0; k < K_NEI; k++) {
        cp_wait<1>();          // group k complete
        __syncthreads();

        const int buf = k & 1;
        const float*  xb = xs + buf * XS_FLOATS + (w * 32) * XS_STRIDE;
        const float2* wb = ws + buf * 2048;

        #pragma unroll
        for (int s = 0; s < 8; s++) {
            const float* ap0 = xb + g * XS_STRIDE + s * 8 + tig;
            const float* ap1 = ap0 + 16 * XS_STRIDE;
            uint32_t a00 = __float_as_uint(ap0[0]);
            uint32_t a02 = __float_as_uint(ap0[4]);
            uint32_t a01 = __float_as_uint(ap0[8 * XS_STRIDE]);
            uint32_t a03 = __float_as_uint(ap0[8 * XS_STRIDE + 4]);
            uint32_t a10 = __float_as_uint(ap1[0]);
            uint32_t a12 = __float_as_uint(ap1[4]);
            uint32_t a11 = __float_as_uint(ap1[8 * XS_STRIDE]);
            uint32_t a13 = __float_as_uint(ap1[8 * XS_STRIDE + 4]);
            #pragma unroll
            for (int c = 0; c < 8; c++) {
                float2 b = wb[(s * 8 + c) * 32 + l];
                uint32_t b0 = __float_as_uint(b.x), b1 = __float_as_uint(b.y);
                mma_tf32(acc[0][c], a00, a01, a02, a03, b0, b1);
                mma_tf32(acc[1][c], a10, a11, a12, a13, b0, b1);
            }
        }
        __syncthreads();       // all warps done with buf before refill
        if (k + 2 < K_NEI) issue(k + 2);
    }

    // ---- epilogue: bias (+tvec) (+resid), direct STG ------------------------
    #pragma unroll
    for (int ti = 0; ti < 2; ti++) {
        const int r0 = base + w * 32 + ti * 16 + g;
        const int r1 = r0 + 8;
        const float* tvp0 = nullptr; const float* tvp1 = nullptr;
        if (tvec) {
            tvp0 = tvec + (size_t)bid[r0] * 64;
            tvp1 = tvec + (size_t)bid[r1] * 64;
        }
        #pragma unroll
        for (int c = 0; c < 8; c++) {
            int co = c * 8 + 2 * tig;
            float2 bb = *reinterpret_cast<const float2*>(bias + co);
            float2 o0 = make_float2(acc[ti][c][0] + bb.x, acc[ti][c][1] + bb.y);
            float2 o1 = make_float2(acc[ti][c][2] + bb.x, acc[ti][c][3] + bb.y);
            if (tvec) {
                float2 tv0 = *reinterpret_cast<const float2*>(tvp0 + co);
                float2 tv1 = *reinterpret_cast<const float2*>(tvp1 + co);
                o0.x += tv0.x; o0.y += tv0.y;
                o1.x += tv1.x; o1.y += tv1.y;
            }
            if (resid) {
                float2 q0 = *reinterpret_cast<const float2*>(resid + (size_t)r0 * 64 + co);
                float2 q1 = *reinterpret_cast<const float2*>(resid + (size_t)r1 * 64 + co);
                o0.x += q0.x; o0.y += q0.y;
                o1.x += q1.x; o1.y += q1.y;
            }
            *reinterpret_cast<float2*>(out + (size_t)r0 * 64 + co) = o0;
            *reinterpret_cast<float2*>(out + (size_t)r1 * 64 + co) = o1;
        }
    }
}

// ---------------- launch ------------------------------------------------------
extern "C" void kernel_launch(void* const* d_in, const int* in_sizes, int n_in,
                              void* d_out, int out_size) {
    const float* x    = (const float*)d_in[0];
    const float* temb = (const float*)d_in[1];
    const int*   bid  = (const int*)  d_in[2];
    const int*   nei  = (const int*)  d_in[3];
    const float* ga1  = (const float*)d_in[4];
    const float* be1  = (const float*)d_in[5];
    const float* W1   = (const float*)d_in[6];
    const float* b1   = (const float*)d_in[7];
    const float* Wt   = (const float*)d_in[8];
    const float* bt   = (const float*)d_in[9];
    const float* ga2  = (const float*)d_in[10];
    const float* be2  = (const float*)d_in[11];
    const float* W2   = (const float*)d_in[12];
    const float* b2   = (const float*)d_in[13];
    float* out = (float*)d_out;

    float *h1, *h2, *sum, *ssq, *cnt, *scale, *shift, *tvec;
    float2 *w1f, *w2f;
    cudaGetSymbolAddress((void**)&h1,    g_h1);
    cudaGetSymbolAddress((void**)&h2,    g_h2);
    cudaGetSymbolAddress((void**)&w1f,   g_w1f);
    cudaGetSymbolAddress((void**)&w2f,   g_w2f);
    cudaGetSymbolAddress((void**)&sum,   g_sum);
    cudaGetSymbolAddress((void**)&ssq,   g_ssq);
    cudaGetSymbolAddress((void**)&cnt,   g_cnt);
    cudaGetSymbolAddress((void**)&scale, g_scale);
    cudaGetSymbolAddress((void**)&shift, g_shift);
    cudaGetSymbolAddress((void**)&tvec,  g_tvec);

    cudaFuncSetAttribute(conv_mma_kernel,
                         cudaFuncAttributeMaxDynamicSharedMemorySize, SM_TOTAL);

    const int statsBlocks = N_NODES / 512;
    const int naBlocks    = (N_NODES * 16) / 256;
    const int convBlocks  = N_NODES / TN;                    // 512
    const int prepBlocks  = (K_NEI * 2048 + 255) / 256;      // 216

    // independent prep
    prep_w_kernel<<<prepBlocks, 256>>>(W1, w1f);
    prep_w_kernel<<<prepBlocks, 256>>>(W2, w2f);
    time_kernel<<<1, 512>>>(temb, Wt, bt, tvec);

    // GN1 -> silu -> h1 (tf32-rounded)
    zero_kernel<<<1, 512>>>(sum, ssq, cnt);
    stats_kernel<<<statsBlocks, 256>>>(x, bid, sum, ssq, cnt, 1);
    finalize_kernel<<<1, 512>>>(sum, ssq, cnt, ga1, be1, scale, shift, 1);
    normact_kernel<<<naBlocks, 256>>>((const float4*)x, bid,
                                      (const float4*)scale, (const float4*)shift,
                                      (float4*)h1);

    // conv1 (tf32 mma.sync) + t[batch] -> h2
    conv_mma_kernel<<<convBlocks, 256, SM_TOTAL>>>(h1, nei, w1f, b1, tvec, bid, nullptr, h2);

    // GN2 -> silu -> h1
    stats_kernel<<<statsBlocks, 256>>>(h2, bid, sum, ssq, cnt, 0);
    finalize_kernel<<<1, 512>>>(sum, ssq, cnt, ga2, be2, scale, shift, 0);
    normact_kernel<<<naBlocks, 256>>>((const float4*)h2, bid,
                                      (const float4*)scale, (const float4*)shift,
                                      (float4*)h1);

    // conv2 (tf32 mma.sync) + residual -> out
    conv_mma_kernel<<<convBlocks, 256, SM_TOTAL>>>(h1, nei, w2f, b2, nullptr, bid, x, out);
}

// round 5
// speedup vs baseline: 4.1534x; 1.5177x over previous
#include <cuda_runtime.h>
#include <cstdint>

#define N_NODES 131072
#define C_DIM   64
#define K_NEI   27
#define B_DIM   8
#define EMB_DIM 512
#define GN_EPS  1e-5f

// ---------------- scratch (device globals; no allocation allowed) -----------
__device__ float  g_h1[N_NODES * C_DIM];
__device__ float  g_h2[N_NODES * C_DIM];
__device__ float2 g_w1f[K_NEI * 2048];     // W1 in B-fragment order (tf32-rounded)
__device__ float2 g_w2f[K_NEI * 2048];     // W2 in B-fragment order
__device__ float  g_sum[B_DIM * C_DIM];
__device__ float  g_ssq[B_DIM * C_DIM];
__device__ float  g_cnt[B_DIM];
__device__ float  g_scale[B_DIM * C_DIM];
__device__ float  g_shift[B_DIM * C_DIM];
__device__ float  g_tvec[B_DIM * C_DIM];

// ---------------- helpers ----------------------------------------------------
__device__ __forceinline__ uint32_t smem_u32(const void* p) {
    uint32_t a;
    asm("{ .reg .u64 t; cvta.to.shared.u64 t, %1; cvt.u32.u64 %0, t; }" : "=r"(a) : "l"(p));
    return a;
}
__device__ __forceinline__ void cp16(uint32_t dst, const void* src) {
    asm volatile("cp.async.cg.shared.global [%0], [%1], 16;" :: "r"(dst), "l"(src) : "memory");
}
__device__ __forceinline__ void cp_commit() {
    asm volatile("cp.async.commit_group;" ::: "memory");
}
template <int N>
__device__ __forceinline__ void cp_wait() {
    asm volatile("cp.async.wait_group %0;" :: "n"(N) : "memory");
}
__device__ __forceinline__ float tf32r(float v) {
    uint32_t r;
    asm("cvt.rna.tf32.f32 %0, %1;" : "=r"(r) : "f"(v));
    return __uint_as_float(r);
}
__device__ __forceinline__ void mma_tf32(float* d, uint32_t a0, uint32_t a1, uint32_t a2,
                                         uint32_t a3, uint32_t b0, uint32_t b1) {
    asm volatile(
        "mma.sync.aligned.m16n8k8.row.col.f32.tf32.tf32.f32 "
        "{%0,%1,%2,%3}, {%4,%5,%6,%7}, {%8,%9}, {%0,%1,%2,%3};"
        : "+f"(d[0]), "+f"(d[1]), "+f"(d[2]), "+f"(d[3])
        : "r"(a0), "r"(a1), "r"(a2), "r"(a3), "r"(b0), "r"(b1));
}
__device__ __forceinline__ float silu_f(float v) { return v / (1.0f + __expf(-v)); }

// ---------------- GN helper kernels ------------------------------------------
__global__ void zero_kernel(float* gsum, float* gssq, float* gcnt) {
    int i = threadIdx.x;
    gsum[i] = 0.0f; gssq[i] = 0.0f;
    if (i < B_DIM) gcnt[i] = 0.0f;
}

__global__ void stats_kernel(const float* __restrict__ in, const int* __restrict__ bid,
                             float* __restrict__ gsum, float* __restrict__ gssq,
                             float* __restrict__ gcnt, int do_cnt) {
    const int NPB = 512;
    int c = threadIdx.x & 63, r = threadIdx.x >> 6;
    int base = blockIdx.x * NPB;
    float s = 0.0f, ss = 0.0f, cl = 0.0f;
    int cur = bid[base + r];
    for (int i = 0; i < NPB / 4; i++) {
        int n = base + i * 4 + r;
        int b = bid[n];
        if (b != cur) {
            atomicAdd(&gsum[cur * 64 + c], s);
            atomicAdd(&gssq[cur * 64 + c], ss);
            if (do_cnt && c == 0) atomicAdd(&gcnt[cur], cl);
            s = 0.0f; ss = 0.0f; cl = 0.0f; cur = b;
        }
        float v = in[(size_t)n * 64 + c];
        s += v; ss += v * v; cl += 1.0f;
    }
    atomicAdd(&gsum[cur * 64 + c], s);
    atomicAdd(&gssq[cur * 64 + c], ss);
    if (do_cnt && c == 0) atomicAdd(&gcnt[cur], cl);
}

__global__ void finalize_kernel(float* __restrict__ gsum, float* __restrict__ gssq,
                                const float* __restrict__ gcnt,
                                const float* __restrict__ gamma, const float* __restrict__ beta,
                                float* __restrict__ scale, float* __restrict__ shift,
                                int zero_after) {
    int i = threadIdx.x;
    int b = i >> 6, c = i & 63;
    int g0 = c & ~1;
    float denom = gcnt[b] * 2.0f;
    float m = (gsum[b * 64 + g0] + gsum[b * 64 + g0 + 1]) / denom;
    float v = (gssq[b * 64 + g0] + gssq[b * 64 + g0 + 1]) / denom - m * m;
    float rs = rsqrtf(v + GN_EPS);
    float sc = gamma[c] * rs;
    scale[i] = sc;
    shift[i] = beta[c] - m * sc;
    if (zero_after) {
        __syncthreads();
        gsum[i] = 0.0f;
        gssq[i] = 0.0f;
    }
}

__global__ void normact_kernel(const float4* __restrict__ in, const int* __restrict__ bid,
                               const float4* __restrict__ scale, const float4* __restrict__ shift,
                               float4* __restrict__ out) {
    int idx = blockIdx.x * blockDim.x + threadIdx.x;
    int n = idx >> 4, q = idx & 15;
    int b = bid[n];
    float4 v = in[idx];
    float4 sc = scale[b * 16 + q];
    float4 sh = shift[b * 16 + q];
    float4 r;
    r.x = tf32r(silu_f(v.x * sc.x + sh.x));
    r.y = tf32r(silu_f(v.y * sc.y + sh.y));
    r.z = tf32r(silu_f(v.z * sc.z + sh.z));
    r.w = tf32r(silu_f(v.w * sc.w + sh.w));
    out[idx] = r;
}

__global__ void time_kernel(const float* __restrict__ emb, const float* __restrict__ Wt,
                            const float* __restrict__ bt, float* __restrict__ tout) {
    __shared__ float se[B_DIM * EMB_DIM];
    int t = threadIdx.x;
    for (int i = t; i < B_DIM * EMB_DIM; i += 512) se[i] = silu_f(emb[i]);
    __syncthreads();
    int b = t >> 6, co = t & 63;
    float acc = bt[co];
    const float* e = se + b * EMB_DIM;
    #pragma unroll 8
    for (int k = 0; k < EMB_DIM; k++) acc += e[k] * Wt[k * 64 + co];
    tout[t] = acc;
}

// ---------------- weight prep: W[k][ci][co] -> B-fragment order (tf32) -------
__global__ void prep_w_kernel(const float* __restrict__ W, float2* __restrict__ Wf) {
    int i = blockIdx.x * 256 + threadIdx.x;      // over K_NEI*2048
    if (i >= K_NEI * 2048) return;
    int k = i >> 11;
    int r = i & 2047;
    int grp = r >> 5, lane = r & 31;
    int s = grp >> 3, c = grp & 7;
    int ci = s * 8 + (lane & 3);
    int co = c * 8 + (lane >> 2);
    const float* wk = W + (size_t)k * 4096;
    float2 v;
    v.x = tf32r(wk[ci * 64 + co]);
    v.y = tf32r(wk[(ci + 4) * 64 + co]);
    Wf[i] = v;
}

// ---------------- tf32 mma.sync gather-conv ----------------------------------
// 128 nodes/block, 256 threads (8 warps x 16 rows), 2 CTAs/SM.
// Warp-coalesced gather staging (2 full rows per cp.async warp-op) and
// XOR-swizzled unpadded A buffer (stride 64 floats).
#define TN        128
#define XS_FLOATS (TN * 64)                   // 8192 floats / buffer (32KB)
#define WS_OFF    0                           // float2 ws[2][2048] : 32KB
#define XS_OFF    32768                       // float  xs[2][8192] : 64KB
#define NB_OFF    (32768 + 65536)             // int snb[27][128]   : 13824B
#define SM_TOTAL  (NB_OFF + K_NEI * TN * 4)   // 112128

__global__ void __launch_bounds__(256, 2) conv_mma_kernel(
    const float* __restrict__ h, const int* __restrict__ neigh,
    const float2* __restrict__ wf, const float* __restrict__ bias,
    const float* __restrict__ tvec, const int* __restrict__ bid,
    const float* __restrict__ resid, float* __restrict__ out)
{
    extern __shared__ char smem[];
    float2* ws = reinterpret_cast<float2*>(smem + WS_OFF);
    float*  xs = reinterpret_cast<float*>(smem + XS_OFF);
    int*    snb = reinterpret_cast<int*>(smem + NB_OFF);
    const uint32_t ws_sm = smem_u32(smem + WS_OFF);
    const uint32_t xs_sm = smem_u32(smem + XS_OFF);

    const int t = threadIdx.x;
    const int w = t >> 5, l = t & 31;
    const int base = blockIdx.x * TN;

    // ---- transpose-load neighbor ids: snb[k][row] (coalesced gmem read) ----
    {
        const int* nsrc = neigh + (size_t)base * K_NEI;
        for (int i = t; i < TN * K_NEI; i += 256) {
            int node = i / K_NEI;
            int kk = i - node * K_NEI;
            snb[kk * TN + node] = nsrc[i];
        }
    }
    __syncthreads();

    float acc[8][4];
    #pragma unroll
    for (int c = 0; c < 8; c++)
        #pragma unroll
        for (int j = 0; j < 4; j++) acc[c][j] = 0.0f;

    const int half  = l >> 4;      // 0/1: which of the 2 rows in this warp-op
    const int chunk = l & 15;      // 16B chunk within the 256B row

    // ---- stage k into buffer (k&1): warp-coalesced ------------------------
    auto issue = [&](int k) {
        const int buf = k & 1;
        // weights: 16KB linear, 4x16B per thread (contiguous per warp)
        {
            const char* src = reinterpret_cast<const char*>(wf + (size_t)k * 2048) + t * 64;
            uint32_t dst = ws_sm + buf * 16384 + t * 64;
            #pragma unroll
            for (int j = 0; j < 4; j++) cp16(dst + j * 16, src + j * 16);
        }
        // gather: warp w stages its own rows w*16..w*16+15; 2 rows per instr
        {
            const int* nbk = snb + k * TN;
            #pragma unroll
            for (int i = 0; i < 8; i++) {
                int row = w * 16 + 2 * i + half;
                int nbv = nbk[row];
                const char* src = reinterpret_cast<const char*>(h + (size_t)nbv * 64)
                                  + chunk * 16;
                uint32_t dst = xs_sm + buf * 32768 + row * 256
                               + ((chunk ^ (row & 7)) << 4);
                cp16(dst, src);
            }
        }
        cp_commit();
    };

    issue(0);
    issue(1);

    const int g = l >> 2, tig = l & 3;

    for (int k = 0; k < K_NEI; k++) {
        cp_wait<1>();          // group k complete
        __syncthreads();

        const int buf = k & 1;
        const float*  xb = xs + buf * XS_FLOATS + (w * 16) * 64;
        const float2* wb = ws + buf * 2048;
        const float*  rp = xb + g * 64;

        #pragma unroll
        for (int s = 0; s < 8; s++) {
            int ph  = (s * 8 + tig) ^ (g << 2);
            int ph2 = ph ^ 4;
            uint32_t a0 = __float_as_uint(rp[ph]);
            uint32_t a2 = __float_as_uint(rp[ph2]);
            uint32_t a1 = __float_as_uint(rp[512 + ph]);
            uint32_t a3 = __float_as_uint(rp[512 + ph2]);
            #pragma unroll
            for (int c = 0; c < 8; c++) {
                float2 b = wb[(s * 8 + c) * 32 + l];
                mma_tf32(acc[c], a0, a1, a2, a3,
                         __float_as_uint(b.x), __float_as_uint(b.y));
            }
        }
        __syncthreads();       // all warps done with buf before refill
        if (k + 2 < K_NEI) issue(k + 2);
    }

    // ---- epilogue: bias (+tvec) (+resid), direct STG ------------------------
    {
        const int r0 = base + w * 16 + g;
        const int r1 = r0 + 8;
        const float* tvp0 = nullptr; const float* tvp1 = nullptr;
        if (tvec) {
            tvp0 = tvec + (size_t)bid[r0] * 64;
            tvp1 = tvec + (size_t)bid[r1] * 64;
        }
        #pragma unroll
        for (int c = 0; c < 8; c++) {
            int co = c * 8 + 2 * tig;
            float2 bb = *reinterpret_cast<const float2*>(bias + co);
            float2 o0 = make_float2(acc[c][0] + bb.x, acc[c][1] + bb.y);
            float2 o1 = make_float2(acc[c][2] + bb.x, acc[c][3] + bb.y);
            if (tvec) {
                float2 tv0 = *reinterpret_cast<const float2*>(tvp0 + co);
                float2 tv1 = *reinterpret_cast<const float2*>(tvp1 + co);
                o0.x += tv0.x; o0.y += tv0.y;
                o1.x += tv1.x; o1.y += tv1.y;
            }
            if (resid) {
                float2 q0 = *reinterpret_cast<const float2*>(resid + (size_t)r0 * 64 + co);
                float2 q1 = *reinterpret_cast<const float2*>(resid + (size_t)r1 * 64 + co);
                o0.x += q0.x; o0.y += q0.y;
                o1.x += q1.x; o1.y += q1.y;
            }
            *reinterpret_cast<float2*>(out + (size_t)r0 * 64 + co) = o0;
            *reinterpret_cast<float2*>(out + (size_t)r1 * 64 + co) = o1;
        }
    }
}

// ---------------- launch ------------------------------------------------------
extern "C" void kernel_launch(void* const* d_in, const int* in_sizes, int n_in,
                              void* d_out, int out_size) {
    const float* x    = (const float*)d_in[0];
    const float* temb = (const float*)d_in[1];
    const int*   bid  = (const int*)  d_in[2];
    const int*   nei  = (const int*)  d_in[3];
    const float* ga1  = (const float*)d_in[4];
    const float* be1  = (const float*)d_in[5];
    const float* W1   = (const float*)d_in[6];
    const float* b1   = (const float*)d_in[7];
    const float* Wt   = (const float*)d_in[8];
    const float* bt   = (const float*)d_in[9];
    const float* ga2  = (const float*)d_in[10];
    const float* be2  = (const float*)d_in[11];
    const float* W2   = (const float*)d_in[12];
    const float* b2   = (const float*)d_in[13];
    float* out = (float*)d_out;

    float *h1, *h2, *sum, *ssq, *cnt, *scale, *shift, *tvec;
    float2 *w1f, *w2f;
    cudaGetSymbolAddress((void**)&h1,    g_h1);
    cudaGetSymbolAddress((void**)&h2,    g_h2);
    cudaGetSymbolAddress((void**)&w1f,   g_w1f);
    cudaGetSymbolAddress((void**)&w2f,   g_w2f);
    cudaGetSymbolAddress((void**)&sum,   g_sum);
    cudaGetSymbolAddress((void**)&ssq,   g_ssq);
    cudaGetSymbolAddress((void**)&cnt,   g_cnt);
    cudaGetSymbolAddress((void**)&scale, g_scale);
    cudaGetSymbolAddress((void**)&shift, g_shift);
    cudaGetSymbolAddress((void**)&tvec,  g_tvec);

    cudaFuncSetAttribute(conv_mma_kernel,
                         cudaFuncAttributeMaxDynamicSharedMemorySize, SM_TOTAL);

    const int statsBlocks = N_NODES / 512;
    const int naBlocks    = (N_NODES * 16) / 256;
    const int convBlocks  = N_NODES / TN;                    // 1024
    const int prepBlocks  = (K_NEI * 2048 + 255) / 256;      // 216

    // independent prep
    prep_w_kernel<<<prepBlocks, 256>>>(W1, w1f);
    prep_w_kernel<<<prepBlocks, 256>>>(W2, w2f);
    time_kernel<<<1, 512>>>(temb, Wt, bt, tvec);

    // GN1 -> silu -> h1 (tf32-rounded)
    zero_kernel<<<1, 512>>>(sum, ssq, cnt);
    stats_kernel<<<statsBlocks, 256>>>(x, bid, sum, ssq, cnt, 1);
    finalize_kernel<<<1, 512>>>(sum, ssq, cnt, ga1, be1, scale, shift, 1);
    normact_kernel<<<naBlocks, 256>>>((const float4*)x, bid,
                                      (const float4*)scale, (const float4*)shift,
                                      (float4*)h1);

    // conv1 (tf32 mma.sync) + t[batch] -> h2
    conv_mma_kernel<<<convBlocks, 256, SM_TOTAL>>>(h1, nei, w1f, b1, tvec, bid, nullptr, h2);

    // GN2 -> silu -> h1
    stats_kernel<<<statsBlocks, 256>>>(h2, bid, sum, ssq, cnt, 0);
    finalize_kernel<<<1, 512>>>(sum, ssq, cnt, ga2, be2, scale, shift, 0);
    normact_kernel<<<naBlocks, 256>>>((const float4*)h2, bid,
                                      (const float4*)scale, (const float4*)shift,
                                      (float4*)h1);

    // conv2 (tf32 mma.sync) + residual -> out
    conv_mma_kernel<<<convBlocks, 256, SM_TOTAL>>>(h1, nei, w2f, b2, nullptr, bid, x, out);
}